// round 12
// baseline (speedup 1.0000x reference)
#include <cuda_runtime.h>
#include <cuda_bf16.h>
#include <cstdint>
#include <cstddef>

// Problem constants
#define NB 16
#define NT 1024
#define ND 256
// DS = 4

#define BM 128
#define LDSK 136       // bf16 elems per A/B smem row for K=128 chunk (272B, odd 16B stride -> ldmatrix conflict-free)
#define GS_STRIDE 130  // bf16 stride of G staging tile (odd word stride -> conflict-free column reads)

#define GRAM_SMEM (2 * 128 * LDSK * 2)   // 69632 B (~68 KB) -> 2 CTAs/SM

#define NTILE (NT / BM)                 // 8
#define NPAIR (NTILE * (NTILE + 1) / 2) // 36
#define NSTREAM_CTA 2048                // 8 warps/CTA, 1 (b,t) row per warp

// Scratch (no allocations allowed -> __device__ globals)
__device__ __align__(16) __nv_bfloat16 g_zbf[NB * NT * ND];        // 8.4 MB
__device__ __align__(16) __nv_bfloat16 g_G[(size_t)NB * NT * NT];  // 33.5 MB
__device__ float  g_z2[NB * NT];
__device__ double g_partial[NSTREAM_CTA];
__device__ unsigned int g_count;   // zero-init; self-resets each run (graph-replay safe)

// pair p -> (i,j), i<=j, over 8 tiles
__constant__ int PAIR_I[NPAIR] = {0,0,0,0,0,0,0,0, 1,1,1,1,1,1,1, 2,2,2,2,2,2,
                                  3,3,3,3,3, 4,4,4,4, 5,5,5, 6,6, 7};
__constant__ int PAIR_J[NPAIR] = {0,1,2,3,4,5,6,7, 1,2,3,4,5,6,7, 2,3,4,5,6,7,
                                  3,4,5,6,7, 4,5,6,7, 5,6,7, 6,7, 7};

// ---------------------------------------------------------------------------
// Kernel 0: z -> bf16 copy + per-row sum of squares (z2).
// 4 rows per warp (8 independent float4 loads per lane -> 2x MLP).
// grid = NB*NT/32 = 512 blocks of 256 threads.
// ---------------------------------------------------------------------------
__global__ void prep_kernel(const float* __restrict__ z) {
    const int warp = blockIdx.x * 8 + (threadIdx.x >> 5);
    const int lane = threadIdx.x & 31;
    const int row0 = warp * 4;

    const float4* zr = reinterpret_cast<const float4*>(z) + (size_t)row0 * (ND / 4);
    float4 v[4][2];
    #pragma unroll
    for (int r = 0; r < 4; r++) {
        v[r][0] = zr[r * (ND / 4) + lane];
        v[r][1] = zr[r * (ND / 4) + lane + 32];
    }

    float s[4];
    #pragma unroll
    for (int r = 0; r < 4; r++) {
        s[r] = v[r][0].x*v[r][0].x + v[r][0].y*v[r][0].y + v[r][0].z*v[r][0].z + v[r][0].w*v[r][0].w
             + v[r][1].x*v[r][1].x + v[r][1].y*v[r][1].y + v[r][1].z*v[r][1].z + v[r][1].w*v[r][1].w;
    }
    #pragma unroll
    for (int o = 16; o; o >>= 1) {
        #pragma unroll
        for (int r = 0; r < 4; r++) s[r] += __shfl_xor_sync(0xffffffffu, s[r], o);
    }
    if (lane < 4) g_z2[row0 + lane] = s[lane];

    auto pack = [](float4 x) {
        __nv_bfloat162 lo = __floats2bfloat162_rn(x.x, x.y);
        __nv_bfloat162 hi = __floats2bfloat162_rn(x.z, x.w);
        uint2 p;
        p.x = *reinterpret_cast<uint32_t*>(&lo);
        p.y = *reinterpret_cast<uint32_t*>(&hi);
        return p;
    };
    uint2* d = reinterpret_cast<uint2*>(g_zbf + (size_t)row0 * ND);
    #pragma unroll
    for (int r = 0; r < 4; r++) {
        d[r * (ND / 4) + lane]      = pack(v[r][0]);
        d[r * (ND / 4) + lane + 32] = pack(v[r][1]);
    }
}

// ---------------------------------------------------------------------------
// gram_kernel: one CTA per (batch, tile pair i<=j). K-chunked GEMM, 2 CTAs/SM.
// Writes G(ti,tj) from fragments; G(tj,ti) via smem transpose stage.
// ---------------------------------------------------------------------------
#define LDSM4(r0, r1, r2, r3, addr)                                              \
    asm volatile("ldmatrix.sync.aligned.m8n8.x4.shared.b16 {%0,%1,%2,%3}, [%4];" \
                 : "=r"(r0), "=r"(r1), "=r"(r2), "=r"(r3) : "r"(addr))

#define MMA16816(d, a, b0r, b1r)                                                 \
    asm volatile("mma.sync.aligned.m16n8k16.row.col.f32.bf16.bf16.f32 "          \
                 "{%0,%1,%2,%3}, {%4,%5,%6,%7}, {%8,%9}, {%0,%1,%2,%3};"         \
                 : "+f"(d[0]), "+f"(d[1]), "+f"(d[2]), "+f"(d[3])                \
                 : "r"(a[0]), "r"(a[1]), "r"(a[2]), "r"(a[3]), "r"(b0r), "r"(b1r))

__global__ void __launch_bounds__(256, 2)
gram_kernel() {
    extern __shared__ __align__(16) char sm[];
    __nv_bfloat16* As = reinterpret_cast<__nv_bfloat16*>(sm);
    __nv_bfloat16* Bs = reinterpret_cast<__nv_bfloat16*>(sm + 128 * LDSK * 2);
    __nv_bfloat16* Gst = reinterpret_cast<__nv_bfloat16*>(sm);  // overlays A after GEMM

    const int bb = blockIdx.z;
    const int ti = PAIR_I[blockIdx.x];
    const int tj = PAIR_J[blockIdx.x];
    const int tid = threadIdx.x;
    const int lane = tid & 31;
    const int wid  = tid >> 5;

    const int wm = (wid & 3) * 32;
    const int wn = (wid >> 2) * 64;

    float acc[2][8][4];
    #pragma unroll
    for (int mi = 0; mi < 2; mi++)
        #pragma unroll
        for (int ni = 0; ni < 8; ni++)
            #pragma unroll
            for (int r = 0; r < 4; r++) acc[mi][ni][r] = 0.f;

    const uint32_t aBase = (uint32_t)__cvta_generic_to_shared(As);
    const uint32_t bBase = (uint32_t)__cvta_generic_to_shared(Bs);
    const uint32_t aAddr0 = aBase + (((wm + (lane & 15)) * LDSK + (lane >> 4) * 8)) * 2;
    const uint32_t bAddr0 = bBase + (((wn + (lane & 7) + ((lane >> 4) << 3)) * LDSK
                                     + ((lane >> 3) & 1) * 8)) * 2;

    const int4* gzt = reinterpret_cast<const int4*>(g_zbf + ((size_t)bb * NT + ti * BM) * ND);
    const int4* gzs = reinterpret_cast<const int4*>(g_zbf + ((size_t)bb * NT + tj * BM) * ND);

    #pragma unroll
    for (int kc = 0; kc < 2; kc++) {
        #pragma unroll
        for (int i = 0; i < 8; i++) {
            int idx = tid + i * 256;          // 0..2047
            int r = idx >> 4, c = idx & 15;
            *reinterpret_cast<int4*>(As + r * LDSK + c * 8) = gzt[r * 32 + kc * 16 + c];
            *reinterpret_cast<int4*>(Bs + r * LDSK + c * 8) = gzs[r * 32 + kc * 16 + c];
        }
        __syncthreads();

        #pragma unroll
        for (int kk = 0; kk < 8; kk++) {
            uint32_t a[2][4];
            #pragma unroll
            for (int mi = 0; mi < 2; mi++) {
                uint32_t addr = aAddr0 + (uint32_t)(mi * 16 * LDSK * 2) + (uint32_t)(kk * 32);
                LDSM4(a[mi][0], a[mi][1], a[mi][2], a[mi][3], addr);
            }
            uint32_t bf[8][2];
            #pragma unroll
            for (int nj = 0; nj < 4; nj++) {
                uint32_t addr = bAddr0 + (uint32_t)(nj * 16 * LDSK * 2) + (uint32_t)(kk * 32);
                uint32_t r0, r1, r2, r3;
                LDSM4(r0, r1, r2, r3, addr);
                bf[2 * nj][0] = r0;     bf[2 * nj][1] = r1;
                bf[2 * nj + 1][0] = r2; bf[2 * nj + 1][1] = r3;
            }
            #pragma unroll
            for (int mi = 0; mi < 2; mi++)
                #pragma unroll
                for (int ni = 0; ni < 8; ni++)
                    MMA16816(acc[mi][ni], a[mi], bf[ni][0], bf[ni][1]);
        }
        __syncthreads();
    }

    // ---- write G(ti,tj) rows from fragments; stage for transpose ----
    const int rowc = lane >> 2;
    const int colc = (lane & 3) * 2;
    #pragma unroll
    for (int mi = 0; mi < 2; mi++)
        #pragma unroll
        for (int h = 0; h < 2; h++) {
            const int row = wm + mi * 16 + rowc + h * 8;
            #pragma unroll
            for (int ni = 0; ni < 8; ni++) {
                const int col = wn + ni * 8 + colc;
                __nv_bfloat162 v = __floats2bfloat162_rn(acc[mi][ni][h * 2 + 0],
                                                         acc[mi][ni][h * 2 + 1]);
                *reinterpret_cast<__nv_bfloat162*>(
                    g_G + ((size_t)(bb * NT + ti * BM + row)) * NT + tj * BM + col) = v;
                if (ti != tj)
                    *reinterpret_cast<__nv_bfloat162*>(Gst + row * GS_STRIDE + col) = v;
            }
        }

    // ---- transpose write G(tj,ti) from staged tile ----
    if (ti != tj) {
        __syncthreads();
        #pragma unroll
        for (int i = 0; i < 8; i++) {
            int idx = tid + i * 256;          // 0..2047
            int rp = idx >> 4, c16 = idx & 15;
            __align__(16) __nv_bfloat16 v[8];
            #pragma unroll
            for (int k = 0; k < 8; k++)
                v[k] = Gst[(c16 * 8 + k) * GS_STRIDE + rp];
            *reinterpret_cast<uint4*>(
                g_G + ((size_t)(bb * NT + tj * BM + rp)) * NT + ti * BM + c16 * 8)
                = *reinterpret_cast<uint4*>(v);
        }
    }
}

// ---------------------------------------------------------------------------
// stream_kernel: coalesced streamer + fused last-block finalize.
// Warp owns one (b,t) row; step s = step*32 + lane (warp reads 512B gt, 64B G).
// gt uses __ldcs (zero reuse); G uses default load (L2-resident from gram).
// Last CTA to finish reduces all partials in FIXED order -> deterministic.
// ---------------------------------------------------------------------------
__global__ void __launch_bounds__(256)
stream_kernel(const float* __restrict__ gt, const float* __restrict__ sigma,
              float* __restrict__ out) {
    const int tid = threadIdx.x;
    const int lane = tid & 31;
    const int wid  = tid >> 5;
    const int bt = blockIdx.x * 8 + wid;      // 0..16383
    const int b = bt >> 10, t = bt & 1023;

    const float sg0 = sigma[0], sg1 = sigma[1], sg2 = sigma[2], sg3 = sigma[3];
    const float inv0 = 1.0f / (2.0f * sg0 * sg0);
    const float inv1 = 1.0f / (2.0f * sg1 * sg1);
    const float inv2 = 1.0f / (2.0f * sg2 * sg2);
    const float inv3 = 1.0f / (2.0f * sg3 * sg3);

    const size_t rowbase = ((size_t)b * NT + t) * NT;
    const float4* gp = reinterpret_cast<const float4*>(gt) + rowbase + lane;
    const unsigned short* Gp = reinterpret_cast<const unsigned short*>(g_G + rowbase) + lane;
    const float z2t = g_z2[b * NT + t];

    float part = 0.f;
    #pragma unroll
    for (int c = 0; c < 4; c++) {
        float4 g[8];
        unsigned short Gq[8];
        #pragma unroll
        for (int u = 0; u < 8; u++) {
            g[u]  = __ldcs(gp + (c * 8 + u) * 32);
            Gq[u] = Gp[(c * 8 + u) * 32];     // default policy: let it hit L2
        }
        #pragma unroll
        for (int u = 0; u < 8; u++) {
            float q = g[u].x * g[u].x * inv0 + g[u].y * g[u].y * inv1
                    + g[u].z * g[u].z * inv2 + g[u].w * g[u].w * inv3;
            float w = __expf(q);
            float Gv = __bfloat162float(*reinterpret_cast<__nv_bfloat16*>(&Gq[u]));
            part += w * (z2t - Gv);
        }
    }

    // ---- CTA reduction (deterministic) ----
    #pragma unroll
    for (int o = 16; o; o >>= 1) part += __shfl_xor_sync(0xffffffffu, part, o);
    __shared__ double red[8];
    if (lane == 0) red[wid] = (double)part;
    __syncthreads();
    if (tid == 0) {
        double ssum = 0.0;
        #pragma unroll
        for (int i = 0; i < 8; i++) ssum += red[i];
        g_partial[blockIdx.x] = ssum;
    }

    // ---- fused finalize: last CTA reduces all partials in fixed order ----
    __shared__ bool isLast;
    __threadfence();
    if (tid == 0) {
        unsigned int c = atomicAdd(&g_count, 1u);
        isLast = (c == (unsigned int)(gridDim.x - 1));
    }
    __syncthreads();
    if (isLast) {
        __shared__ double fred[256];
        double v = 0.0;
        for (int i = tid; i < NSTREAM_CTA; i += 256) v += g_partial[i];
        fred[tid] = v;
        __syncthreads();
        for (int off = 128; off; off >>= 1) {
            if (tid < off) fred[tid] += fred[tid + off];
            __syncthreads();
        }
        if (tid == 0) {
            out[0] = (float)(fred[0] * (2.0 / ((double)NB * (double)NT * (double)NT)));
            g_count = 0;   // reset for next graph replay
        }
    }
}

// ---------------------------------------------------------------------------
extern "C" void kernel_launch(void* const* d_in, const int* in_sizes, int n_in,
                              void* d_out, int out_size) {
    const float* z     = (const float*)d_in[0];  // [16,1024,256]
    const float* gt    = (const float*)d_in[1];  // [16,1024,1024,4]
    const float* sigma = (const float*)d_in[2];  // [4]
    float* out = (float*)d_out;

    cudaFuncSetAttribute(gram_kernel, cudaFuncAttributeMaxDynamicSharedMemorySize, GRAM_SMEM);

    prep_kernel<<<NB * NT / 32, 256>>>(z);
    gram_kernel<<<dim3(NPAIR, 1, NB), 256, GRAM_SMEM>>>();
    stream_kernel<<<NSTREAM_CTA, 256>>>(gt, sigma, out);
}

// round 13
// speedup vs baseline: 1.0455x; 1.0455x over previous
#include <cuda_runtime.h>
#include <cuda_bf16.h>
#include <cstdint>
#include <cstddef>

// Problem constants
#define NB 16
#define NT 1024
#define ND 256
// DS = 4

#define BM 128
#define LDSK 136       // bf16 elems per A/B smem row for K=128 chunk (272B, odd 16B stride -> ldmatrix conflict-free)
#define GS_STRIDE 130  // bf16 stride of G staging tile (odd word stride -> conflict-free column reads)

#define GRAM_SMEM (2 * 128 * LDSK * 2)   // 69632 B (~68 KB) -> 2 CTAs/SM

#define NTILE (NT / BM)                 // 8
#define NPAIR (NTILE * (NTILE + 1) / 2) // 36
#define NSTREAM_CTA 2048                // 8 warps/CTA, 1 (b,t) row per warp

// Scratch (no allocations allowed -> __device__ globals)
__device__ __align__(16) __nv_bfloat16 g_zbf[NB * NT * ND];        // 8.4 MB
__device__ __align__(16) __nv_bfloat16 g_G[(size_t)NB * NT * NT];  // 33.5 MB
__device__ float  g_z2[NB * NT];
__device__ double g_partial[NSTREAM_CTA];
__device__ unsigned int g_count;   // zero-init; self-resets each run (graph-replay safe)

// pair p -> (i,j), i<=j, over 8 tiles
__constant__ int PAIR_I[NPAIR] = {0,0,0,0,0,0,0,0, 1,1,1,1,1,1,1, 2,2,2,2,2,2,
                                  3,3,3,3,3, 4,4,4,4, 5,5,5, 6,6, 7};
__constant__ int PAIR_J[NPAIR] = {0,1,2,3,4,5,6,7, 1,2,3,4,5,6,7, 2,3,4,5,6,7,
                                  3,4,5,6,7, 4,5,6,7, 5,6,7, 6,7, 7};

// ---------------------------------------------------------------------------
// Kernel 0 (R1-proven variant): z -> bf16 + per-row sum of squares.
// 2 rows per warp; grid = NB*NT/16 = 1024 blocks of 256 threads.
// ---------------------------------------------------------------------------
__global__ void prep_kernel(const float* __restrict__ z) {
    const int warp = blockIdx.x * 8 + (threadIdx.x >> 5);
    const int lane = threadIdx.x & 31;
    const int row0 = warp * 2;

    const float4* zr0 = reinterpret_cast<const float4*>(z) + (size_t)row0 * (ND / 4);
    const float4* zr1 = zr0 + (ND / 4);
    float4 a0 = zr0[lane];
    float4 a1 = zr0[lane + 32];
    float4 b0 = zr1[lane];
    float4 b1 = zr1[lane + 32];

    float s0 = a0.x*a0.x + a0.y*a0.y + a0.z*a0.z + a0.w*a0.w
             + a1.x*a1.x + a1.y*a1.y + a1.z*a1.z + a1.w*a1.w;
    float s1 = b0.x*b0.x + b0.y*b0.y + b0.z*b0.z + b0.w*b0.w
             + b1.x*b1.x + b1.y*b1.y + b1.z*b1.z + b1.w*b1.w;
    #pragma unroll
    for (int o = 16; o; o >>= 1) {
        s0 += __shfl_xor_sync(0xffffffffu, s0, o);
        s1 += __shfl_xor_sync(0xffffffffu, s1, o);
    }
    if (lane == 0) { g_z2[row0] = s0; g_z2[row0 + 1] = s1; }

    uint2* d0 = reinterpret_cast<uint2*>(g_zbf + (size_t)row0 * ND);
    uint2* d1 = d0 + (ND / 4);
    auto pack = [](float4 v) {
        __nv_bfloat162 lo = __floats2bfloat162_rn(v.x, v.y);
        __nv_bfloat162 hi = __floats2bfloat162_rn(v.z, v.w);
        uint2 p;
        p.x = *reinterpret_cast<uint32_t*>(&lo);
        p.y = *reinterpret_cast<uint32_t*>(&hi);
        return p;
    };
    d0[lane]      = pack(a0);
    d0[lane + 32] = pack(a1);
    d1[lane]      = pack(b0);
    d1[lane + 32] = pack(b1);
}

// ---------------------------------------------------------------------------
// gram_kernel: one CTA per (batch, tile pair i<=j). K-chunked GEMM, 2 CTAs/SM.
// Writes G(ti,tj) from fragments; G(tj,ti) via smem transpose stage.
// ---------------------------------------------------------------------------
#define LDSM4(r0, r1, r2, r3, addr)                                              \
    asm volatile("ldmatrix.sync.aligned.m8n8.x4.shared.b16 {%0,%1,%2,%3}, [%4];" \
                 : "=r"(r0), "=r"(r1), "=r"(r2), "=r"(r3) : "r"(addr))

#define MMA16816(d, a, b0r, b1r)                                                 \
    asm volatile("mma.sync.aligned.m16n8k16.row.col.f32.bf16.bf16.f32 "          \
                 "{%0,%1,%2,%3}, {%4,%5,%6,%7}, {%8,%9}, {%0,%1,%2,%3};"         \
                 : "+f"(d[0]), "+f"(d[1]), "+f"(d[2]), "+f"(d[3])                \
                 : "r"(a[0]), "r"(a[1]), "r"(a[2]), "r"(a[3]), "r"(b0r), "r"(b1r))

__global__ void __launch_bounds__(256, 2)
gram_kernel() {
    extern __shared__ __align__(16) char sm[];
    __nv_bfloat16* As = reinterpret_cast<__nv_bfloat16*>(sm);
    __nv_bfloat16* Bs = reinterpret_cast<__nv_bfloat16*>(sm + 128 * LDSK * 2);
    __nv_bfloat16* Gst = reinterpret_cast<__nv_bfloat16*>(sm);  // overlays A after GEMM

    const int bb = blockIdx.z;
    const int ti = PAIR_I[blockIdx.x];
    const int tj = PAIR_J[blockIdx.x];
    const int tid = threadIdx.x;
    const int lane = tid & 31;
    const int wid  = tid >> 5;

    const int wm = (wid & 3) * 32;
    const int wn = (wid >> 2) * 64;

    float acc[2][8][4];
    #pragma unroll
    for (int mi = 0; mi < 2; mi++)
        #pragma unroll
        for (int ni = 0; ni < 8; ni++)
            #pragma unroll
            for (int r = 0; r < 4; r++) acc[mi][ni][r] = 0.f;

    const uint32_t aBase = (uint32_t)__cvta_generic_to_shared(As);
    const uint32_t bBase = (uint32_t)__cvta_generic_to_shared(Bs);
    const uint32_t aAddr0 = aBase + (((wm + (lane & 15)) * LDSK + (lane >> 4) * 8)) * 2;
    const uint32_t bAddr0 = bBase + (((wn + (lane & 7) + ((lane >> 4) << 3)) * LDSK
                                     + ((lane >> 3) & 1) * 8)) * 2;

    const int4* gzt = reinterpret_cast<const int4*>(g_zbf + ((size_t)bb * NT + ti * BM) * ND);
    const int4* gzs = reinterpret_cast<const int4*>(g_zbf + ((size_t)bb * NT + tj * BM) * ND);

    #pragma unroll
    for (int kc = 0; kc < 2; kc++) {
        #pragma unroll
        for (int i = 0; i < 8; i++) {
            int idx = tid + i * 256;          // 0..2047
            int r = idx >> 4, c = idx & 15;
            *reinterpret_cast<int4*>(As + r * LDSK + c * 8) = gzt[r * 32 + kc * 16 + c];
            *reinterpret_cast<int4*>(Bs + r * LDSK + c * 8) = gzs[r * 32 + kc * 16 + c];
        }
        __syncthreads();

        #pragma unroll
        for (int kk = 0; kk < 8; kk++) {
            uint32_t a[2][4];
            #pragma unroll
            for (int mi = 0; mi < 2; mi++) {
                uint32_t addr = aAddr0 + (uint32_t)(mi * 16 * LDSK * 2) + (uint32_t)(kk * 32);
                LDSM4(a[mi][0], a[mi][1], a[mi][2], a[mi][3], addr);
            }
            uint32_t bf[8][2];
            #pragma unroll
            for (int nj = 0; nj < 4; nj++) {
                uint32_t addr = bAddr0 + (uint32_t)(nj * 16 * LDSK * 2) + (uint32_t)(kk * 32);
                uint32_t r0, r1, r2, r3;
                LDSM4(r0, r1, r2, r3, addr);
                bf[2 * nj][0] = r0;     bf[2 * nj][1] = r1;
                bf[2 * nj + 1][0] = r2; bf[2 * nj + 1][1] = r3;
            }
            #pragma unroll
            for (int mi = 0; mi < 2; mi++)
                #pragma unroll
                for (int ni = 0; ni < 8; ni++)
                    MMA16816(acc[mi][ni], a[mi], bf[ni][0], bf[ni][1]);
        }
        __syncthreads();
    }

    // ---- write G(ti,tj) rows from fragments; stage for transpose ----
    const int rowc = lane >> 2;
    const int colc = (lane & 3) * 2;
    #pragma unroll
    for (int mi = 0; mi < 2; mi++)
        #pragma unroll
        for (int h = 0; h < 2; h++) {
            const int row = wm + mi * 16 + rowc + h * 8;
            #pragma unroll
            for (int ni = 0; ni < 8; ni++) {
                const int col = wn + ni * 8 + colc;
                __nv_bfloat162 v = __floats2bfloat162_rn(acc[mi][ni][h * 2 + 0],
                                                         acc[mi][ni][h * 2 + 1]);
                *reinterpret_cast<__nv_bfloat162*>(
                    g_G + ((size_t)(bb * NT + ti * BM + row)) * NT + tj * BM + col) = v;
                if (ti != tj)
                    *reinterpret_cast<__nv_bfloat162*>(Gst + row * GS_STRIDE + col) = v;
            }
        }

    // ---- transpose write G(tj,ti) from staged tile ----
    if (ti != tj) {
        __syncthreads();
        #pragma unroll
        for (int i = 0; i < 8; i++) {
            int idx = tid + i * 256;          // 0..2047
            int rp = idx >> 4, c16 = idx & 15;
            __align__(16) __nv_bfloat16 v[8];
            #pragma unroll
            for (int k = 0; k < 8; k++)
                v[k] = Gst[(c16 * 8 + k) * GS_STRIDE + rp];
            *reinterpret_cast<uint4*>(
                g_G + ((size_t)(bb * NT + tj * BM + rp)) * NT + ti * BM + c16 * 8)
                = *reinterpret_cast<uint4*>(v);
        }
    }
}

// ---------------------------------------------------------------------------
// stream_kernel: coalesced streamer + smem-staged G + fused last-block finalize.
// Warp owns one (b,t) row (16 KB gt, 2 KB G).
//   - G row staged to smem via 4 x LDG.128/lane (coalesced), read via LDS.U16
//     (lanes within 64B window -> same-word pairs, conflict-free).
//   - gt read with __ldcs, s = step*32 + lane (warp: 512B/instr).
// Last CTA reduces partials in FIXED order -> deterministic, replay-safe.
// ---------------------------------------------------------------------------
__global__ void __launch_bounds__(256)
stream_kernel(const float* __restrict__ gt, const float* __restrict__ sigma,
              float* __restrict__ out) {
    __shared__ __align__(16) unsigned short sG[8][1024];   // 16 KB
    const int tid = threadIdx.x;
    const int lane = tid & 31;
    const int wid  = tid >> 5;
    const int bt = blockIdx.x * 8 + wid;      // 0..16383
    const int b = bt >> 10, t = bt & 1023;

    const float sg0 = sigma[0], sg1 = sigma[1], sg2 = sigma[2], sg3 = sigma[3];
    const float inv0 = 1.0f / (2.0f * sg0 * sg0);
    const float inv1 = 1.0f / (2.0f * sg1 * sg1);
    const float inv2 = 1.0f / (2.0f * sg2 * sg2);
    const float inv3 = 1.0f / (2.0f * sg3 * sg3);

    const size_t rowbase = ((size_t)b * NT + t) * NT;
    const float4* gp = reinterpret_cast<const float4*>(gt) + rowbase + lane;
    const float z2t = g_z2[b * NT + t];

    // ---- stage this warp's G row (2 KB) into smem, coalesced ----
    {
        const uint4* Gv4 = reinterpret_cast<const uint4*>(g_G + rowbase);
        uint4 q[4];
        #pragma unroll
        for (int it = 0; it < 4; it++) q[it] = Gv4[lane + it * 32];
        #pragma unroll
        for (int it = 0; it < 4; it++)
            reinterpret_cast<uint4*>(sG[wid])[lane + it * 32] = q[it];
    }
    __syncwarp();

    float part = 0.f;
    #pragma unroll
    for (int c = 0; c < 4; c++) {
        float4 g[8];
        #pragma unroll
        for (int u = 0; u < 8; u++)
            g[u] = __ldcs(gp + (c * 8 + u) * 32);
        #pragma unroll
        for (int u = 0; u < 8; u++) {
            float q = g[u].x * g[u].x * inv0 + g[u].y * g[u].y * inv1
                    + g[u].z * g[u].z * inv2 + g[u].w * g[u].w * inv3;
            float w = __expf(q);
            unsigned short Gq = sG[wid][lane + (c * 8 + u) * 32];
            float Gv = __bfloat162float(*reinterpret_cast<__nv_bfloat16*>(&Gq));
            part += w * (z2t - Gv);
        }
    }

    // ---- CTA reduction (deterministic) ----
    #pragma unroll
    for (int o = 16; o; o >>= 1) part += __shfl_xor_sync(0xffffffffu, part, o);
    __shared__ double red[8];
    if (lane == 0) red[wid] = (double)part;
    __syncthreads();
    if (tid == 0) {
        double ssum = 0.0;
        #pragma unroll
        for (int i = 0; i < 8; i++) ssum += red[i];
        g_partial[blockIdx.x] = ssum;
    }

    // ---- fused finalize: last CTA reduces all partials in fixed order ----
    __shared__ bool isLast;
    __threadfence();
    if (tid == 0) {
        unsigned int c = atomicAdd(&g_count, 1u);
        isLast = (c == (unsigned int)(gridDim.x - 1));
    }
    __syncthreads();
    if (isLast) {
        __shared__ double fred[256];
        double v = 0.0;
        for (int i = tid; i < NSTREAM_CTA; i += 256) v += g_partial[i];
        fred[tid] = v;
        __syncthreads();
        for (int off = 128; off; off >>= 1) {
            if (tid < off) fred[tid] += fred[tid + off];
            __syncthreads();
        }
        if (tid == 0) {
            out[0] = (float)(fred[0] * (2.0 / ((double)NB * (double)NT * (double)NT)));
            g_count = 0;   // reset for next graph replay
        }
    }
}

// ---------------------------------------------------------------------------
extern "C" void kernel_launch(void* const* d_in, const int* in_sizes, int n_in,
                              void* d_out, int out_size) {
    const float* z     = (const float*)d_in[0];  // [16,1024,256]
    const float* gt    = (const float*)d_in[1];  // [16,1024,1024,4]
    const float* sigma = (const float*)d_in[2];  // [4]
    float* out = (float*)d_out;

    cudaFuncSetAttribute(gram_kernel, cudaFuncAttributeMaxDynamicSharedMemorySize, GRAM_SMEM);

    prep_kernel<<<NB * NT / 16, 256>>>(z);
    gram_kernel<<<dim3(NPAIR, 1, NB), 256, GRAM_SMEM>>>();
    stream_kernel<<<NSTREAM_CTA, 256>>>(gt, sigma, out);
}